// round 17
// baseline (speedup 1.0000x reference)
#include <cuda_runtime.h>
#include <cuda_bf16.h>
#include <mma.h>
#include <math.h>

using namespace nvcuda;

#define B_    32
#define H_    32
#define D_    128
#define HID_  4096
#define TH_   12288      // 3*HID
#define BS_   64
#define NBLK_ 16
#define KSPLIT 8
#define KSPLITO 4
#define NCHUNK 8

__device__ float g_part[KSPLIT][B_ * TH_];  // qkv partials (reused by oproj)
__device__ float g_qkv[B_ * TH_];           // [b][j]; j<4096 q, ..8191 k, .. v
__device__ float g_cs[B_][64][2];           // rope cos/sin table
__device__ __nv_bfloat16 g_hhi[B_ * HID_];
__device__ __nv_bfloat16 g_hlo[B_ * HID_];
__device__ __nv_bfloat16 g_ahi[B_ * HID_];
__device__ __nv_bfloat16 g_alo[B_ * HID_];
__device__ float g_pm[NCHUNK][B_ * H_];
__device__ float g_pl[NCHUNK][B_ * H_];
__device__ float g_pacc[NCHUNK][B_ * H_ * D_];

__device__ __forceinline__ unsigned bfpack(float f0, float f1) {
    __nv_bfloat162 p = __floats2bfloat162_rn(f0, f1);
    return *(unsigned*)&p;
}
__device__ __forceinline__ float bflow(unsigned w)  { return __uint_as_float(w << 16); }
__device__ __forceinline__ float bfhigh(unsigned w) { return __uint_as_float(w & 0xffff0000u); }

// ---------------------------------------------------------------------------
// Kernel 0: split hidden into bf16 hi/lo; blocks 0-31 also fill rope table.
// ---------------------------------------------------------------------------
__global__ __launch_bounds__(256) void hsplit_kernel(const float* __restrict__ hidden,
                                                     const int* __restrict__ hist) {
    int i = blockIdx.x * 256 + threadIdx.x;
    float x = hidden[i];
    __nv_bfloat16 hi = __float2bfloat16(x);
    g_hhi[i] = hi;
    g_hlo[i] = __float2bfloat16(x - __bfloat162float(hi));

    if (blockIdx.x < 32 && threadIdx.x < 64) {
        const int b = blockIdx.x;
        const int f = threadIdx.x;
        double invd = exp(-(double)f / 64.0 * 9.210340371976184);  // ln(10000)
        double angd = fmod((double)hist[b] * invd, 6.283185307179586476925286766559);
        g_cs[b][f][0] = cosf((float)angd);
        g_cs[b][f][1] = sinf((float)angd);
    }
}

// ---------------------------------------------------------------------------
// Kernel 1: qkv split-bf16 WMMA. 128 threads, 4 warps, warp = 32 j-cols
// (2 n-tiles x 2 m-tiles = 4 accumulators): halves redundant A-frag loads.
// grid (96 j-tiles, KSPLIT=8).
// ---------------------------------------------------------------------------
__global__ __launch_bounds__(128) void qkv_wmma_kernel(const float* __restrict__ W) {
    __shared__ __align__(16) __nv_bfloat16 s_whi[2][32][136];
    __shared__ __align__(16) __nv_bfloat16 s_wlo[2][32][136];
    __shared__ __align__(16) __nv_bfloat16 s_ahi[2][32][40];
    __shared__ __align__(16) __nv_bfloat16 s_alo[2][32][40];
    const int tid = threadIdx.x;
    const int wid = tid >> 5;          // 0..3
    const int n0  = wid * 32;
    const int j0  = blockIdx.x * 128;
    const int k0  = blockIdx.y * (HID_ / KSPLIT);   // 512

    wmma::fragment<wmma::accumulator, 16, 16, 16, float> acc00, acc01, acc10, acc11;
    wmma::fill_fragment(acc00, 0.f);
    wmma::fill_fragment(acc01, 0.f);
    wmma::fill_fragment(acc10, 0.f);
    wmma::fill_fragment(acc11, 0.f);

    const float* wbase = W + j0;
    const int arow = tid >> 2;            // 0..31
    const int acol = (tid & 3) * 8;       // 0,8,16,24

#define QSTAGE(BUF)                                                              \
    _Pragma("unroll")                                                            \
    for (int t = 0; t < 8; t++) {                                                \
        int idx = tid + t * 128;                                                 \
        int row = idx >> 5;                                                      \
        int col = (idx & 31) * 4;                                                \
        float4 w4 = wreg[t];                                                     \
        unsigned hA = bfpack(w4.x, w4.y);                                        \
        unsigned hB = bfpack(w4.z, w4.w);                                        \
        unsigned lA = bfpack(w4.x - bflow(hA), w4.y - bfhigh(hA));               \
        unsigned lB = bfpack(w4.z - bflow(hB), w4.w - bfhigh(hB));               \
        *(uint2*)&s_whi[BUF][row][col] = make_uint2(hA, hB);                     \
        *(uint2*)&s_wlo[BUF][row][col] = make_uint2(lA, lB);                     \
    }

    float4 wreg[8];
#pragma unroll
    for (int t = 0; t < 8; t++) {
        int idx = tid + t * 128;
        wreg[t] = *(const float4*)&wbase[(size_t)(k0 + (idx >> 5)) * TH_ + (idx & 31) * 4];
    }
    {
        uint4 ah = *(const uint4*)&g_hhi[arow * HID_ + k0 + acol];
        uint4 al = *(const uint4*)&g_hlo[arow * HID_ + k0 + acol];
        QSTAGE(0)
        *(uint4*)&s_ahi[0][arow][acol] = ah;
        *(uint4*)&s_alo[0][arow][acol] = al;
    }
#pragma unroll
    for (int t = 0; t < 8; t++) {
        int idx = tid + t * 128;
        wreg[t] = *(const float4*)&wbase[(size_t)(k0 + 32 + (idx >> 5)) * TH_ + (idx & 31) * 4];
    }
    __syncthreads();

    for (int ph = 0; ph < 16; ph++) {
        const int buf = ph & 1;
        const int nbf = buf ^ 1;
        if (ph < 15) {
            uint4 ah = *(const uint4*)&g_hhi[arow * HID_ + k0 + (ph + 1) * 32 + acol];
            uint4 al = *(const uint4*)&g_hlo[arow * HID_ + k0 + (ph + 1) * 32 + acol];
            if (nbf) { QSTAGE(1) } else { QSTAGE(0) }
            *(uint4*)&s_ahi[nbf][arow][acol] = ah;
            *(uint4*)&s_alo[nbf][arow][acol] = al;
            if (ph < 14) {
#pragma unroll
                for (int t = 0; t < 8; t++) {
                    int idx = tid + t * 128;
                    wreg[t] = *(const float4*)&wbase[(size_t)(k0 + (ph + 2) * 32 + (idx >> 5)) * TH_ + (idx & 31) * 4];
                }
            }
        }

#pragma unroll
        for (int kt = 0; kt < 2; kt++) {
            wmma::fragment<wmma::matrix_a, 16, 16, 16, __nv_bfloat16, wmma::row_major> ahi0, ahi1, alo0, alo1;
            wmma::fragment<wmma::matrix_b, 16, 16, 16, __nv_bfloat16, wmma::row_major> bhi0, bhi1, blo0, blo1;
            wmma::load_matrix_sync(ahi0, &s_ahi[buf][0][kt * 16], 40);
            wmma::load_matrix_sync(ahi1, &s_ahi[buf][16][kt * 16], 40);
            wmma::load_matrix_sync(alo0, &s_alo[buf][0][kt * 16], 40);
            wmma::load_matrix_sync(alo1, &s_alo[buf][16][kt * 16], 40);
            wmma::load_matrix_sync(bhi0, &s_whi[buf][kt * 16][n0], 136);
            wmma::load_matrix_sync(bhi1, &s_whi[buf][kt * 16][n0 + 16], 136);
            wmma::load_matrix_sync(blo0, &s_wlo[buf][kt * 16][n0], 136);
            wmma::load_matrix_sync(blo1, &s_wlo[buf][kt * 16][n0 + 16], 136);
            wmma::mma_sync(acc00, ahi0, bhi0, acc00);
            wmma::mma_sync(acc01, ahi0, bhi1, acc01);
            wmma::mma_sync(acc10, ahi1, bhi0, acc10);
            wmma::mma_sync(acc11, ahi1, bhi1, acc11);
            wmma::mma_sync(acc00, alo0, bhi0, acc00);
            wmma::mma_sync(acc01, alo0, bhi1, acc01);
            wmma::mma_sync(acc10, alo1, bhi0, acc10);
            wmma::mma_sync(acc11, alo1, bhi1, acc11);
            wmma::mma_sync(acc00, ahi0, blo0, acc00);
            wmma::mma_sync(acc01, ahi0, blo1, acc01);
            wmma::mma_sync(acc10, ahi1, blo0, acc10);
            wmma::mma_sync(acc11, ahi1, blo1, acc11);
        }
        __syncthreads();
    }
#undef QSTAGE

    float* outp = &g_part[blockIdx.y][0];
    wmma::store_matrix_sync(&outp[j0 + n0], acc00, TH_, wmma::mem_row_major);
    wmma::store_matrix_sync(&outp[j0 + n0 + 16], acc01, TH_, wmma::mem_row_major);
    wmma::store_matrix_sync(&outp[(size_t)16 * TH_ + j0 + n0], acc10, TH_, wmma::mem_row_major);
    wmma::store_matrix_sync(&outp[(size_t)16 * TH_ + j0 + n0 + 16], acc11, TH_, wmma::mem_row_major);
}

// ---------------------------------------------------------------------------
// Kernel 2: reduce KSPLIT partials + apply RoPE inline. grid 256 x 256.
// ---------------------------------------------------------------------------
__global__ __launch_bounds__(256) void qkv_reduce_rope(int dummy) {
    const int t = blockIdx.x * 256 + threadIdx.x;
    if (t < 32768) {
        const int b    = t >> 10;
        const int rem  = t & 1023;
        const int part = rem >> 9;
        const int rem2 = rem & 511;
        const int h    = rem2 >> 4;
        const int dq   = rem2 & 15;
        const int d0   = dq * 4;
        const int idx_lo = b * TH_ + part * HID_ + h * D_ + d0;
        const int idx_hi = idx_lo + 64;

        float4 rl = *(const float4*)&g_part[0][idx_lo];
        float4 rh = *(const float4*)&g_part[0][idx_hi];
#pragma unroll
        for (int p = 1; p < KSPLIT; p++) {
            float4 a = *(const float4*)&g_part[p][idx_lo];
            float4 c = *(const float4*)&g_part[p][idx_hi];
            rl.x += a.x; rl.y += a.y; rl.z += a.z; rl.w += a.w;
            rh.x += c.x; rh.y += c.y; rh.z += c.z; rh.w += c.w;
        }
        float4 cs0 = *(const float4*)&g_cs[b][d0][0];
        float4 cs1 = *(const float4*)&g_cs[b][d0 + 2][0];
        float4 ol, oh;
        ol.x = rl.x * cs0.x - rh.x * cs0.y;  oh.x = rh.x * cs0.x + rl.x * cs0.y;
        ol.y = rl.y * cs0.z - rh.y * cs0.w;  oh.y = rh.y * cs0.z + rl.y * cs0.w;
        ol.z = rl.z * cs1.x - rh.z * cs1.y;  oh.z = rh.z * cs1.x + rl.z * cs1.y;
        ol.w = rl.w * cs1.z - rh.w * cs1.w;  oh.w = rh.w * cs1.z + rl.w * cs1.w;
        *(float4*)&g_qkv[idx_lo] = ol;
        *(float4*)&g_qkv[idx_hi] = oh;
    } else {
        const int t2  = t - 32768;
        const int b   = t2 >> 10;
        const int off = (t2 & 1023) * 4;
        const int idx = b * TH_ + 2 * HID_ + off;
        float4 r = *(const float4*)&g_part[0][idx];
#pragma unroll
        for (int p = 1; p < KSPLIT; p++) {
            float4 a = *(const float4*)&g_part[p][idx];
            r.x += a.x; r.y += a.y; r.z += a.z; r.w += a.w;
        }
        *(float4*)&g_qkv[idx] = r;
    }
}

// ---------------------------------------------------------------------------
// Kernel 3a: split-KV attention partials (R16). grid (B*H, NCHUNK), 256 thr.
// ---------------------------------------------------------------------------
__global__ __launch_bounds__(256) void attn_part_kernel(const float* __restrict__ kcache,
                                                        const float* __restrict__ vcache,
                                                        const int* __restrict__ hist,
                                                        const int* __restrict__ boff) {
    const int bh = blockIdx.x;
    const int c  = blockIdx.y;
    const int b  = bh >> 5;
    const int h  = bh & 31;
    const int tid  = threadIdx.x;
    const int lane = tid & 31;
    const int wid  = tid >> 5;

    const int pos  = hist[b];
    const int base = c * 128;
    if (base > pos) return;
    const int cachedLen = min(128, pos - base);
    const bool hasFresh = (pos - base) < 128;

    __shared__ int   s_blk[NBLK_];
    __shared__ float s_sc[128];
    __shared__ float s_red[8];
    __shared__ float s_acc[8][128];

    if (tid < NBLK_) s_blk[tid] = boff[b * NBLK_ + tid];
    __syncthreads();

    const float scale = 0.08838834764831845f;   // 1/sqrt(128)
    const float4 q4 = *(const float4*)&g_qkv[b * TH_ + h * D_ + lane * 4];

    float mloc = -1e30f;
    int j = wid;
    for (; j + 56 < cachedLen; j += 64) {
        float4 k[8];
#pragma unroll
        for (int u = 0; u < 8; u++) {
            int s = base + j + u * 8;
            int a = ((s_blk[s >> 6] * BS_ + (s & 63)) * H_ + h) * D_;
            k[u] = *(const float4*)&kcache[a + lane * 4];
        }
        float dt[8];
#pragma unroll
        for (int u = 0; u < 8; u++)
            dt[u] = q4.x * k[u].x + q4.y * k[u].y + q4.z * k[u].z + q4.w * k[u].w;
#pragma unroll
        for (int o = 16; o > 0; o >>= 1)
#pragma unroll
            for (int u = 0; u < 8; u++)
                dt[u] += __shfl_xor_sync(0xffffffffu, dt[u], o);
#pragma unroll
        for (int u = 0; u < 8; u++) {
            dt[u] *= scale;
            mloc = fmaxf(mloc, dt[u]);
            if (lane == 0) s_sc[j + u * 8] = dt[u];
        }
    }
    for (; j < cachedLen; j += 8) {
        int s = base + j;
        int a = ((s_blk[s >> 6] * BS_ + (s & 63)) * H_ + h) * D_;
        float4 k0 = *(const float4*)&kcache[a + lane * 4];
        float d0 = q4.x * k0.x + q4.y * k0.y + q4.z * k0.z + q4.w * k0.w;
#pragma unroll
        for (int o = 16; o > 0; o >>= 1) d0 += __shfl_xor_sync(0xffffffffu, d0, o);
        d0 *= scale;
        mloc = fmaxf(mloc, d0);
        if (lane == 0) s_sc[j] = d0;
    }
    if (hasFresh && ((pos - base) & 7) == wid) {
        const float* kp = &g_qkv[b * TH_ + HID_ + h * D_];
        float4 k0 = *(const float4*)&kp[lane * 4];
        float d0 = q4.x * k0.x + q4.y * k0.y + q4.z * k0.z + q4.w * k0.w;
#pragma unroll
        for (int o = 16; o > 0; o >>= 1) d0 += __shfl_xor_sync(0xffffffffu, d0, o);
        d0 *= scale;
        mloc = fmaxf(mloc, d0);
        if (lane == 0) s_sc[pos - base] = d0;
    }

    if (lane == 0) s_red[wid] = mloc;
    __syncthreads();
    float M = -1e30f;
#pragma unroll
    for (int w = 0; w < 8; w++) M = fmaxf(M, s_red[w]);

    const int cnt = cachedLen + (hasFresh ? 1 : 0);
    float lsum = 0.f;
    if (tid < cnt) {
        float p = __expf(s_sc[tid] - M);
        s_sc[tid] = p;
        lsum = p;
    }
#pragma unroll
    for (int o = 16; o > 0; o >>= 1) lsum += __shfl_xor_sync(0xffffffffu, lsum, o);
    __syncthreads();
    if (lane == 0) s_red[wid] = lsum;
    __syncthreads();
    float Lc = 0.f;
#pragma unroll
    for (int w = 0; w < 8; w++) Lc += s_red[w];

    float4 a4 = make_float4(0.f, 0.f, 0.f, 0.f);
    j = wid;
    for (; j + 56 < cachedLen; j += 64) {
        float4 v[8];
        float  pr[8];
#pragma unroll
        for (int u = 0; u < 8; u++) {
            int s = base + j + u * 8;
            int a = ((s_blk[s >> 6] * BS_ + (s & 63)) * H_ + h) * D_;
            v[u]  = *(const float4*)&vcache[a + lane * 4];
            pr[u] = s_sc[j + u * 8];
        }
#pragma unroll
        for (int u = 0; u < 8; u++) {
            a4.x += pr[u] * v[u].x;
            a4.y += pr[u] * v[u].y;
            a4.z += pr[u] * v[u].z;
            a4.w += pr[u] * v[u].w;
        }
    }
    for (; j < cachedLen; j += 8) {
        int s = base + j;
        int a = ((s_blk[s >> 6] * BS_ + (s & 63)) * H_ + h) * D_;
        float4 v = *(const float4*)&vcache[a + lane * 4];
        float  p = s_sc[j];
        a4.x += p * v.x; a4.y += p * v.y; a4.z += p * v.z; a4.w += p * v.w;
    }
    if (hasFresh && ((pos - base) & 7) == wid) {
        const float* vp = &g_qkv[b * TH_ + 2 * HID_ + h * D_];
        float4 v = *(const float4*)&vp[lane * 4];
        float  p = s_sc[pos - base];
        a4.x += p * v.x; a4.y += p * v.y; a4.z += p * v.z; a4.w += p * v.w;
    }

    *(float4*)&s_acc[wid][lane * 4] = a4;
    __syncthreads();
    if (tid < 128) {
        float val = 0.f;
#pragma unroll
        for (int w = 0; w < 8; w++) val += s_acc[w][tid];
        g_pacc[c][bh * D_ + tid] = val;
    }
    if (tid == 0) { g_pm[c][bh] = M; g_pl[c][bh] = Lc; }
}

// ---------------------------------------------------------------------------
// Kernel 3b: combine partials -> attn (bf16 hi/lo). grid B*H, 128 thr.
// ---------------------------------------------------------------------------
__global__ __launch_bounds__(128) void attn_combine_kernel(const int* __restrict__ hist) {
    const int bh = blockIdx.x;
    const int b  = bh >> 5;
    const int h  = bh & 31;
    const int tid = threadIdx.x;
    const int pos = hist[b];
    const int nc  = (pos >> 7) + 1;

    __shared__ float sm[NCHUNK], sl[NCHUNK];
    if (tid < nc) { sm[tid] = g_pm[tid][bh]; sl[tid] = g_pl[tid][bh]; }
    __syncthreads();

    float M = -1e30f;
    for (int c = 0; c < nc; c++) M = fmaxf(M, sm[c]);
    float L = 0.f, val = 0.f;
    for (int c = 0; c < nc; c++) {
        float r = __expf(sm[c] - M);
        L   += sl[c] * r;
        val += g_pacc[c][bh * D_ + tid] * r;
    }
    val /= L;
    __nv_bfloat16 hi = __float2bfloat16(val);
    g_ahi[b * HID_ + h * D_ + tid] = hi;
    g_alo[b * HID_ + h * D_ + tid] = __float2bfloat16(val - __bfloat162float(hi));
}

// ---------------------------------------------------------------------------
// Kernel 4: oproj split-bf16 WMMA, 128 threads, 4 warps, warp = 32 i-cols.
// [n][k] staging + col_major B. grid (32 i-tiles, KSPLITO=4).
// ---------------------------------------------------------------------------
__global__ __launch_bounds__(128) void oproj_wmma_kernel(const float* __restrict__ Wo) {
    __shared__ __align__(16) __nv_bfloat16 s_whi[2][128][40];   // [n][k]
    __shared__ __align__(16) __nv_bfloat16 s_wlo[2][128][40];
    __shared__ __align__(16) __nv_bfloat16 s_ahi[2][32][40];
    __shared__ __align__(16) __nv_bfloat16 s_alo[2][32][40];
    const int tid = threadIdx.x;
    const int wid = tid >> 5;
    const int n0  = wid * 32;
    const int i0  = blockIdx.x * 128;
    const int k0  = blockIdx.y * (HID_ / KSPLITO);   // 1024

    wmma::fragment<wmma::accumulator, 16, 16, 16, float> acc00, acc01, acc10, acc11;
    wmma::fill_fragment(acc00, 0.f);
    wmma::fill_fragment(acc01, 0.f);
    wmma::fill_fragment(acc10, 0.f);
    wmma::fill_fragment(acc11, 0.f);

    const int arow = tid >> 2;
    const int acol = (tid & 3) * 8;
    const int wn   = tid;               // 0..127 : n index, full 32-k row

#define OSTAGE(BUF)                                                              \
    _Pragma("unroll")                                                            \
    for (int t = 0; t < 8; t++) {                                                \
        float4 w4 = wreg[t];                                                     \
        int kq = t * 4;                                                          \
        unsigned hA = bfpack(w4.x, w4.y);                                        \
        unsigned hB = bfpack(w4.z, w4.w);                                        \
        unsigned lA = bfpack(w4.x - bflow(hA), w4.y - bfhigh(hA));               \
        unsigned lB = bfpack(w4.z - bflow(hB), w4.w - bfhigh(hB));               \
        *(uint2*)&s_whi[BUF][wn][kq] = make_uint2(hA, hB);                       \
        *(uint2*)&s_wlo[BUF][wn][kq] = make_uint2(lA, lB);                       \
    }

    float4 wreg[8];
#pragma unroll
    for (int t = 0; t < 8; t++)
        wreg[t] = *(const float4*)&Wo[(size_t)(i0 + wn) * HID_ + k0 + t * 4];
    {
        uint4 ah = *(const uint4*)&g_ahi[arow * HID_ + k0 + acol];
        uint4 al = *(const uint4*)&g_alo[arow * HID_ + k0 + acol];
        OSTAGE(0)
        *(uint4*)&s_ahi[0][arow][acol] = ah;
        *(uint4*)&s_alo[0][arow][acol] = al;
    }
#pragma unroll
    for (int t = 0; t < 8; t++)
        wreg[t] = *(const float4*)&Wo[(size_t)(i0 + wn) * HID_ + k0 + 32 + t * 4];
    __syncthreads();

    for (int ph = 0; ph < 32; ph++) {
        const int buf = ph & 1;
        const int nbf = buf ^ 1;
        if (ph < 31) {
            uint4 ah = *(const uint4*)&g_ahi[arow * HID_ + k0 + (ph + 1) * 32 + acol];
            uint4 al = *(const uint4*)&g_alo[arow * HID_ + k0 + (ph + 1) * 32 + acol];
            if (nbf) { OSTAGE(1) } else { OSTAGE(0) }
            *(uint4*)&s_ahi[nbf][arow][acol] = ah;
            *(uint4*)&s_alo[nbf][arow][acol] = al;
            if (ph < 30) {
#pragma unroll
                for (int t = 0; t < 8; t++)
                    wreg[t] = *(const float4*)&Wo[(size_t)(i0 + wn) * HID_ + k0 + (ph + 2) * 32 + t * 4];
            }
        }

#pragma unroll
        for (int kt = 0; kt < 2; kt++) {
            wmma::fragment<wmma::matrix_a, 16, 16, 16, __nv_bfloat16, wmma::row_major> ahi0, ahi1, alo0, alo1;
            wmma::fragment<wmma::matrix_b, 16, 16, 16, __nv_bfloat16, wmma::col_major> bhi0, bhi1, blo0, blo1;
            wmma::load_matrix_sync(ahi0, &s_ahi[buf][0][kt * 16], 40);
            wmma::load_matrix_sync(ahi1, &s_ahi[buf][16][kt * 16], 40);
            wmma::load_matrix_sync(alo0, &s_alo[buf][0][kt * 16], 40);
            wmma::load_matrix_sync(alo1, &s_alo[buf][16][kt * 16], 40);
            wmma::load_matrix_sync(bhi0, &s_whi[buf][n0][kt * 16], 40);
            wmma::load_matrix_sync(bhi1, &s_whi[buf][n0 + 16][kt * 16], 40);
            wmma::load_matrix_sync(blo0, &s_wlo[buf][n0][kt * 16], 40);
            wmma::load_matrix_sync(blo1, &s_wlo[buf][n0 + 16][kt * 16], 40);
            wmma::mma_sync(acc00, ahi0, bhi0, acc00);
            wmma::mma_sync(acc01, ahi0, bhi1, acc01);
            wmma::mma_sync(acc10, ahi1, bhi0, acc10);
            wmma::mma_sync(acc11, ahi1, bhi1, acc11);
            wmma::mma_sync(acc00, alo0, bhi0, acc00);
            wmma::mma_sync(acc01, alo0, bhi1, acc01);
            wmma::mma_sync(acc10, alo1, bhi0, acc10);
            wmma::mma_sync(acc11, alo1, bhi1, acc11);
            wmma::mma_sync(acc00, ahi0, blo0, acc00);
            wmma::mma_sync(acc01, ahi0, blo1, acc01);
            wmma::mma_sync(acc10, ahi1, blo0, acc10);
            wmma::mma_sync(acc11, ahi1, blo1, acc11);
        }
        __syncthreads();
    }
#undef OSTAGE

    float* outp = &g_part[blockIdx.y][0];
    wmma::store_matrix_sync(&outp[i0 + n0], acc00, HID_, wmma::mem_row_major);
    wmma::store_matrix_sync(&outp[i0 + n0 + 16], acc01, HID_, wmma::mem_row_major);
    wmma::store_matrix_sync(&outp[(size_t)16 * HID_ + i0 + n0], acc10, HID_, wmma::mem_row_major);
    wmma::store_matrix_sync(&outp[(size_t)16 * HID_ + i0 + n0 + 16], acc11, HID_, wmma::mem_row_major);
}

// Reduce KSPLITO oproj partials -> out.
__global__ __launch_bounds__(256) void oproj_reduce_kernel(float* __restrict__ out) {
    int i = (blockIdx.x * 256 + threadIdx.x) * 4;
    float4 r = *(const float4*)&g_part[0][i];
#pragma unroll
    for (int p = 1; p < KSPLITO; p++) {
        float4 a = *(const float4*)&g_part[p][i];
        r.x += a.x; r.y += a.y; r.z += a.z; r.w += a.w;
    }
    *(float4*)&out[i] = r;
}

// ---------------------------------------------------------------------------
extern "C" void kernel_launch(void* const* d_in, const int* in_sizes, int n_in,
                              void* d_out, int out_size) {
    const float* hidden = (const float*)d_in[0];
    const float* W      = (const float*)d_in[1];
    const float* Wo     = (const float*)d_in[2];
    const float* kcache = (const float*)d_in[3];
    const float* vcache = (const float*)d_in[4];
    const int*   hist   = (const int*)d_in[5];
    const int*   boff   = (const int*)d_in[6];
    float*       out    = (float*)d_out;

    hsplit_kernel<<<B_ * HID_ / 256, 256>>>(hidden, hist);
    qkv_wmma_kernel<<<dim3(TH_ / 128, KSPLIT), 128>>>(W);
    qkv_reduce_rope<<<256, 256>>>(0);
    attn_part_kernel<<<dim3(B_ * H_, NCHUNK), 256>>>(kcache, vcache, hist, boff);
    attn_combine_kernel<<<B_ * H_, 128>>>(hist);
    oproj_wmma_kernel<<<dim3(HID_ / 128, KSPLITO), 128>>>(Wo);
    oproj_reduce_kernel<<<B_ * HID_ / 1024, 256>>>(out);
}